// round 13
// baseline (speedup 1.0000x reference)
#include <cuda_runtime.h>
#include <cuda_bf16.h>
#include <cuda_fp16.h>
#include <cstdint>

// ---------------------------------------------------------------------------
// SAM spatial self-attention, reduced algebra + HMMA (mma.sync) flash.
//   scores: s_nm = r_n . x_m,  r = log2e*((Wq^T Wk)^T x + Wk^T bq)
//   out:    y = (Wo Wv)(softmax(s) X) + (Wo bv + bo) + x
// QK: bf16 2-way splits, 3 of 4 cross products.
// PV: single fp16 product; fp16-safe via the provable per-query shift
//   s <= ||r_n|| * max_m ||x_m|| (Cauchy-Schwarz), p' = 2^(s-bound+14) <= 2^14.
// R13: attn goes 128->256 threads per CTA (8 warps, 16 query rows per warp,
// m=1 fragments). Same grid, same images, same arithmetic order per output.
// All 256 CTAs were already co-resident at 2 warps/SMSP; this doubles warp
// concurrency to 4/SMSP so softmax/pack phases hide under other warps' HMMA.
// ---------------------------------------------------------------------------

namespace {
constexpr int BATCH = 8, CIN = 32, COUT = 64, NPIX = 4096;
constexpr int MQ  = 128;           // queries per CTA
constexpr int TK  = 64;            // keys per tile
constexpr int NKT = NPIX / TK;     // 64
constexpr float LOG2E = 1.4426950408889634f;
constexpr float OFF   = 14.0f;     // p' <= 2^14 (fp16-safe)
constexpr int KROW_B = 80;                    // 16 data words + 4 pad
constexpr int KIMG_B = 2 * TK * KROW_B;       // 10240 (2 bf16 splits)
constexpr int VROW_B = 144;                   // 32 data words + 4 pad
constexpr int VIMG_B = CIN * VROW_B;          // 4608 (single fp16 image)
// smem layout (attn)
constexpr int SM_K  = 0;                      // 2 x 10240
constexpr int SM_V  = 2 * KIMG_B;             // 20480: 2 x 4608
constexpr int SM_W  = SM_V + 2 * VIMG_B;      // 29696: WovP 4096B
constexpr int SM_B2 = SM_W + 4096;            // 33792: 128B
constexpr int SM_OV = SM_B2 + 128;            // 33920: 128*33*4
constexpr int SM_TOTAL = SM_OV + 128 * 33 * 4; // 50816
}

// global scratch (allocation-free rule; zero-initialized at module load)
__device__ __align__(16) float g_WovP[CIN * CIN];  // [j][c] = (Wo Wv)[c][j]
__device__ __align__(16) float g_b2[CIN];          // Wo bv + bo
__device__ __align__(16) unsigned char g_Kimg[BATCH * NKT * KIMG_B]; // 5.24MB
__device__ __align__(16) unsigned char g_Vimg[BATCH * NKT * VIMG_B]; // 2.36MB
__device__ __align__(16) uint32_t g_Rw[2 * BATCH * NPIX * 16];       // 4MB
__device__ float    g_rn[BATCH * NPIX];            // ||r_n|| (log2e-scaled)
__device__ unsigned g_M2[BATCH];                   // bits of max ||x||^2
// (no reset needed: zero-init at load; atomicMax idempotent across replays)

// ---------------- helpers ----------------
__device__ __forceinline__ void mma_bf16(float* d, const uint32_t* a, const uint32_t* b) {
    asm("mma.sync.aligned.m16n8k16.row.col.f32.bf16.bf16.f32 "
        "{%0,%1,%2,%3}, {%4,%5,%6,%7}, {%8,%9}, {%0,%1,%2,%3};"
        : "+f"(d[0]), "+f"(d[1]), "+f"(d[2]), "+f"(d[3])
        : "r"(a[0]), "r"(a[1]), "r"(a[2]), "r"(a[3]), "r"(b[0]), "r"(b[1]));
}
__device__ __forceinline__ void mma_f16(float* d, const uint32_t* a, const uint32_t* b) {
    asm("mma.sync.aligned.m16n8k16.row.col.f32.f16.f16.f32 "
        "{%0,%1,%2,%3}, {%4,%5,%6,%7}, {%8,%9}, {%0,%1,%2,%3};"
        : "+f"(d[0]), "+f"(d[1]), "+f"(d[2]), "+f"(d[3])
        : "r"(a[0]), "r"(a[1]), "r"(a[2]), "r"(a[3]), "r"(b[0]), "r"(b[1]));
}
__device__ __forceinline__ uint32_t pk_bf(float lo, float hi) {   // {hi:lo}
    uint32_t r;
    asm("cvt.rn.satfinite.bf16x2.f32 %0, %1, %2;" : "=r"(r) : "f"(hi), "f"(lo));
    return r;
}
__device__ __forceinline__ uint32_t pk_f16(float lo, float hi) {  // {hi:lo}
    uint32_t r;
    asm("cvt.rn.f16x2.f32 %0, %1, %2;" : "=r"(r) : "f"(hi), "f"(lo));
    return r;
}
__device__ __forceinline__ float ex2f(float a) {
    float p; asm("ex2.approx.f32 %0, %1;" : "=f"(p) : "f"(a)); return p;
}
__device__ __forceinline__ uint32_t sm_u32(const void* p) {
    uint32_t a;
    asm("{ .reg .u64 t; cvta.to.shared.u64 t, %1; cvt.u32.u64 %0, t; }" : "=r"(a) : "l"(p));
    return a;
}
__device__ __forceinline__ void cp16(uint32_t s, const void* g) {
    asm volatile("cp.async.cg.shared.global [%0], [%1], 16;" :: "r"(s), "l"(g));
}
__device__ __forceinline__ void cp_commit() { asm volatile("cp.async.commit_group;"); }
template<int N> __device__ __forceinline__ void cp_wait() {
    asm volatile("cp.async.wait_group %0;" :: "n"(N));
}

// ---------------------------------------------------------------------------
// Precursor: At/cv in-block, then r-projection + images + norms.
// Block (0,0) additionally computes g_WovP / g_b2 (derive kernel folded here).
// (BYTE-IDENTICAL to R12's tq_kernel.)
// ---------------------------------------------------------------------------
__global__ void tq_kernel(const float* __restrict__ x, const float* __restrict__ wq,
                          const float* __restrict__ bq, const float* __restrict__ wk,
                          const float* __restrict__ wv, const float* __restrict__ wo,
                          const float* __restrict__ bv, const float* __restrict__ bo) {
    __shared__ float sA[CIN * CIN];
    __shared__ float scv[CIN];
    __shared__ float swk[2048], swq[2048];
    int tid = threadIdx.x;                         // 256
    int b = blockIdx.y;
    int n = blockIdx.x * 256 + tid;

    for (int i = tid; i < 2048; i += 256) { swk[i] = wk[i]; swq[i] = wq[i]; }
    __syncthreads();
#pragma unroll
    for (int e = 0; e < 4; ++e) {
        int idx = tid * 4 + e;
        int j = idx >> 5, i = idx & 31;
        float a = 0.f;
#pragma unroll 8
        for (int o = 0; o < COUT; ++o) a += swk[o * 32 + i] * swq[o * 32 + j];
        sA[j * 32 + i] = a * LOG2E;
    }
    if (tid < 32) {
        float c = 0.f;
        for (int o = 0; o < COUT; ++o) c += bq[o] * swk[o * 32 + tid];
        scv[tid] = c * LOG2E;
    }
    __syncthreads();

    // derive-fold: ONE block computes WovP/b2 (swk/swq free for reuse now)
    if (blockIdx.x == 0 && blockIdx.y == 0) {
        for (int i = tid; i < 2048; i += 256) { swk[i] = wv[i]; swq[i] = wo[i]; }
        __syncthreads();
#pragma unroll
        for (int e = 0; e < 4; ++e) {
            int idx = tid * 4 + e;
            int j = idx >> 5, i = idx & 31;
            float w = 0.f;
#pragma unroll 8
            for (int cc = 0; cc < COUT; ++cc) w += swq[j * 64 + cc] * swk[cc * 32 + i];
            g_WovP[i * CIN + j] = w;
        }
        if (tid < 32) {
            float bb = bo[tid];
#pragma unroll 8
            for (int cc = 0; cc < COUT; ++cc) bb += swq[tid * 64 + cc] * bv[cc];
            g_b2[tid] = bb;
        }
    }

    float xv[CIN];
#pragma unroll
    for (int c = 0; c < CIN; ++c) xv[c] = x[((size_t)b * CIN + c) * NPIX + n];
    float r[CIN];
#pragma unroll
    for (int i = 0; i < CIN; ++i) r[i] = scv[i];
#pragma unroll
    for (int j = 0; j < CIN; ++j) {
        float v = xv[j];
#pragma unroll
        for (int i = 0; i < CIN; ++i) r[i] += sA[j * CIN + i] * v;
    }

    // norms for the provable softmax shift
    float nx2 = 0.f, nr2 = 0.f;
#pragma unroll
    for (int c = 0; c < CIN; ++c) { nx2 += xv[c] * xv[c]; nr2 += r[c] * r[c]; }
    atomicMax(&g_M2[b], __float_as_uint(nx2));     // positive floats: uint order
    g_rn[(size_t)b * NPIX + n] = sqrtf(nr2);

    int kt = n >> 6, kl = n & 63;
    uint32_t* K0 = (uint32_t*)(g_Kimg + (size_t)(b * NKT + kt) * KIMG_B) + kl * 20;
    uint32_t* K1 = K0 + TK * 20;
    unsigned char* V0 = g_Vimg + (size_t)(b * NKT + kt) * VIMG_B;
    uint32_t* R0 = g_Rw + ((size_t)b * NPIX + n) * 16;
    uint32_t* R1 = R0 + (size_t)BATCH * NPIX * 16;

#pragma unroll
    for (int w = 0; w < 16; ++w) {
        float va = xv[2 * w], vb = xv[2 * w + 1];
        __nv_bfloat16 a1 = __float2bfloat16(va), b1 = __float2bfloat16(vb);
        float a1f = __bfloat162float(a1), b1f = __bfloat162float(b1);
        K0[w] = pk_bf(a1f, b1f);
        K1[w] = pk_bf(va - a1f, vb - b1f);
        float ra = r[2 * w], rb = r[2 * w + 1];
        __nv_bfloat16 c1 = __float2bfloat16(ra), d1 = __float2bfloat16(rb);
        float c1f = __bfloat162float(c1), d1f = __bfloat162float(d1);
        R0[w] = pk_bf(c1f, d1f);
        R1[w] = pk_bf(ra - c1f, rb - d1f);
    }
    K0[16] = K0[17] = K0[18] = K0[19] = 0u;
    K1[16] = K1[17] = K1[18] = K1[19] = 0u;
#pragma unroll
    for (int c = 0; c < CIN; ++c)
        *(__half*)(V0 + c * VROW_B + kl * 2) = __float2half(xv[c]);
}

// ---------------------------------------------------------------------------
// HMMA flash attention. 256 threads = 8 warps x 16 query rows (m=1 fragments).
// Same grid / images / per-output arithmetic order as R9's measured-best attn;
// only the warp decomposition changes (2x warps per SMSP for phase overlap).
// ---------------------------------------------------------------------------
__global__ __launch_bounds__(256, 2) void attn_kernel(const float* __restrict__ xin,
                                                      float* __restrict__ out) {
    extern __shared__ unsigned char sm[];
    const int tid  = threadIdx.x, wid = tid >> 5, lane = tid & 31;
    const int tg   = lane >> 2, la = lane & 3;
    const int b    = blockIdx.x >> 5, qt = blockIdx.x & 31;
    const uint32_t smb = sm_u32(sm);

    float* sW  = (float*)(sm + SM_W);
    float* sB2 = (float*)(sm + SM_B2);
    float* sOv = (float*)(sm + SM_OV);
    for (int i = tid; i < CIN * CIN; i += 256) sW[i] = g_WovP[i];
    if (tid < CIN) sB2[tid] = g_b2[tid];

    // per-row S init: OFF - ||r_row|| * max||x||  (provable fp16-safe shift)
    const float Mb = sqrtf(__uint_as_float(g_M2[b]));
    float sh[2];
#pragma unroll
    for (int h = 0; h < 2; ++h) {
        int row = qt * MQ + 16 * wid + 8 * h + tg;
        sh[h] = OFF - g_rn[(size_t)b * NPIX + row] * Mb;
    }

    // R fragments (resident): Ra[split][kblk][4]  (16 rows per warp)
    uint32_t Ra[2][2][4];
#pragma unroll
    for (int s = 0; s < 2; ++s) {
        int qr = qt * MQ + 16 * wid + tg;
        const uint32_t* p0 = g_Rw + (((size_t)s * BATCH + b) * NPIX + qr) * 16;
        const uint32_t* p8 = p0 + 8 * 16;
#pragma unroll
        for (int k = 0; k < 2; ++k) {
            Ra[s][k][0] = p0[8 * k + la];
            Ra[s][k][1] = p8[8 * k + la];
            Ra[s][k][2] = p0[8 * k + la + 4];
            Ra[s][k][3] = p8[8 * k + la + 4];
        }
    }

    float O[4][4];
#pragma unroll
    for (int c = 0; c < 4; ++c)
#pragma unroll
        for (int e = 0; e < 4; ++e) O[c][e] = 0.f;
    float l2[2] = {0.f, 0.f};

    // stage tile 0
    {
        const uint4* Ks = (const uint4*)(g_Kimg + (size_t)(b * NKT + 0) * KIMG_B);
        const uint4* Vs = (const uint4*)(g_Vimg + (size_t)(b * NKT + 0) * VIMG_B);
        for (int i = tid; i < KIMG_B / 16; i += 256) cp16(smb + SM_K + i * 16, Ks + i);
        for (int i = tid; i < VIMG_B / 16; i += 256) cp16(smb + SM_V + i * 16, Vs + i);
        cp_commit();
    }

#pragma unroll 1
    for (int t = 0; t < NKT; ++t) {
        if (t + 1 < NKT) {
            int nb = (t + 1) & 1;
            const uint4* Ks = (const uint4*)(g_Kimg + (size_t)(b * NKT + t + 1) * KIMG_B);
            const uint4* Vs = (const uint4*)(g_Vimg + (size_t)(b * NKT + t + 1) * VIMG_B);
            for (int i = tid; i < KIMG_B / 16; i += 256)
                cp16(smb + SM_K + nb * KIMG_B + i * 16, Ks + i);
            for (int i = tid; i < VIMG_B / 16; i += 256)
                cp16(smb + SM_V + nb * VIMG_B + i * 16, Vs + i);
            cp_commit();
            cp_wait<1>();
        } else {
            cp_wait<0>();
        }
        __syncthreads();
        const unsigned char* kb = sm + SM_K + (t & 1) * KIMG_B;
        const unsigned char* vb = sm + SM_V + (t & 1) * VIMG_B;

        // ---- QK: S = R.K^T + (OFF - bound_row)  (3 bf16 split products) ----
        float S[8][4];
#pragma unroll
        for (int j = 0; j < 8; ++j) {
            S[j][0] = sh[0]; S[j][1] = sh[0];
            S[j][2] = sh[1]; S[j][3] = sh[1];
        }

#pragma unroll
        for (int bs = 0; bs < 2; ++bs) {
            uint32_t Bf[8][2][2];
#pragma unroll
            for (int j = 0; j < 8; ++j)
#pragma unroll
                for (int k = 0; k < 2; ++k) {
                    int off = bs * (TK * KROW_B) + ((8 * j + tg) * 20 + 8 * k + la) * 4;
                    Bf[j][k][0] = *(const uint32_t*)(kb + off);
                    Bf[j][k][1] = *(const uint32_t*)(kb + off + 16);
                }
            const int nas = bs ? 1 : 2;   // (R1,K1),(R2,K1),(R1,K2)
            for (int as = 0; as < nas; ++as)
#pragma unroll
                for (int j = 0; j < 8; ++j)
#pragma unroll
                    for (int k = 0; k < 2; ++k)
                        mma_bf16(S[j], Ra[as][k], Bf[j][k]);
        }

        // ---- softmax -> P fp16 fragments (arg <= OFF, overflow-free) ----
        uint32_t P[4][4];
#pragma unroll
        for (int j = 0; j < 8; ++j) {
            float p0 = ex2f(S[j][0]), p1 = ex2f(S[j][1]);
            float p2 = ex2f(S[j][2]), p3 = ex2f(S[j][3]);
            l2[0] += p0 + p1;
            l2[1] += p2 + p3;
            int kk = j >> 1, o = (j & 1) * 2;
            P[kk][o]     = pk_f16(p0, p1);
            P[kk][o + 1] = pk_f16(p2, p3);
        }

        // ---- PV: O += P.V (single fp16 product) ----
        {
            uint32_t Vf[4][4][2];
#pragma unroll
            for (int c = 0; c < 4; ++c)
#pragma unroll
                for (int k = 0; k < 4; ++k) {
                    int off = (8 * c + tg) * VROW_B + (8 * k + la) * 4;
                    Vf[c][k][0] = *(const uint32_t*)(vb + off);
                    Vf[c][k][1] = *(const uint32_t*)(vb + off + 16);
                }
#pragma unroll
            for (int c = 0; c < 4; ++c)
#pragma unroll
                for (int k = 0; k < 4; ++k)
                    mma_f16(O[c], P[k], Vf[c][k]);
        }
        __syncthreads();
    }

    // ---- epilogue: l reduce (across la), normalize, store ov to smem ----
#pragma unroll
    for (int i = 0; i < 2; ++i) {
        l2[i] += __shfl_xor_sync(0xFFFFFFFFu, l2[i], 1);
        l2[i] += __shfl_xor_sync(0xFFFFFFFFu, l2[i], 2);
        asm("rcp.approx.f32 %0, %1;" : "+f"(l2[i]) : "f"(l2[i]));
    }
#pragma unroll
    for (int h = 0; h < 2; ++h) {
        int row = 16 * wid + 8 * h + tg;
        float inv = l2[h];
#pragma unroll
        for (int c = 0; c < 4; ++c) {
            sOv[row * 33 + 8 * c + 2 * la]     = O[c][2 * h]     * inv;
            sOv[row * 33 + 8 * c + 2 * la + 1] = O[c][2 * h + 1] * inv;
        }
    }
    __syncthreads();

    // ---- fused projection + bias + residual (each thread: 1 query, 16 ch) ----
    const int q = tid & 127, hf = tid >> 7;
    float ov[CIN], y[16];
#pragma unroll
    for (int c = 0; c < CIN; ++c) ov[c] = sOv[q * 33 + c];
#pragma unroll
    for (int c = 0; c < 16; ++c) y[c] = sB2[16 * hf + c];
#pragma unroll 4
    for (int j = 0; j < CIN; ++j) {
        float pj = ov[j];
        const float* wp = sW + j * CIN + 16 * hf;
#pragma unroll
        for (int c = 0; c < 16; ++c) y[c] += pj * wp[c];
    }
    int n = qt * MQ + q;
    const float* xp = xin + (size_t)b * CIN * NPIX + n;
    float*       op = out + (size_t)b * CIN * NPIX + n;
#pragma unroll
    for (int c = 0; c < 16; ++c) {
        int ch = 16 * hf + c;
        op[(size_t)ch * NPIX] = y[c] + xp[(size_t)ch * NPIX];
    }
}

// ---------------------------------------------------------------------------
extern "C" void kernel_launch(void* const* d_in, const int* in_sizes, int n_in,
                              void* d_out, int out_size) {
    (void)in_sizes; (void)n_in; (void)out_size;
    const float* x  = (const float*)d_in[0];
    const float* wq = (const float*)d_in[1];
    const float* bq = (const float*)d_in[2];
    const float* wk = (const float*)d_in[3];
    // d_in[4] = bk: cancels in softmax, unused
    const float* wv = (const float*)d_in[5];
    const float* bv = (const float*)d_in[6];
    const float* wo = (const float*)d_in[7];
    const float* bo = (const float*)d_in[8];
    float* out = (float*)d_out;

    cudaFuncSetAttribute(attn_kernel, cudaFuncAttributeMaxDynamicSharedMemorySize, SM_TOTAL);

    tq_kernel<<<dim3(NPIX / 256, BATCH), 256>>>(x, wq, bq, wk, wv, wo, bv, bo);
    attn_kernel<<<BATCH * (NPIX / MQ), 256, SM_TOTAL>>>(x, out);
}

// round 14
// speedup vs baseline: 1.1183x; 1.1183x over previous
#include <cuda_runtime.h>
#include <cuda_bf16.h>
#include <cuda_fp16.h>
#include <cstdint>

// ---------------------------------------------------------------------------
// SAM spatial self-attention, reduced algebra + HMMA (mma.sync) flash.
//   scores: s_nm = r_n . x_m,  r = log2e*((Wq^T Wk)^T x + Wk^T bq)
//   out:    y = (Wo Wv)(softmax(s) X) + (Wo bv + bo) + x
// QK: bf16 2-way splits, 3 of 4 cross products.
// PV: single fp16 product; fp16-safe via the provable per-query shift
//   s <= ||r_n|| * max_m ||x_m|| (Cauchy-Schwarz), p' = 2^(s-bound+14) <= 2^14.
// R14: R12 base (R9's m=2 attn shape, derive folded into tq). ONE change:
// all B/V fragment loads go through ldmatrix.x4 (24 LDSM vs 96 LDS.32 per
// warp-tile; same bytes, same values, conflict-free for 80B/144B rows).
// R13 showed the kernel is issue/LSU-pressure-bound, not warp-starved.
// ---------------------------------------------------------------------------

namespace {
constexpr int BATCH = 8, CIN = 32, COUT = 64, NPIX = 4096;
constexpr int MQ  = 128;           // queries per CTA
constexpr int TK  = 64;            // keys per tile
constexpr int NKT = NPIX / TK;     // 64
constexpr float LOG2E = 1.4426950408889634f;
constexpr float OFF   = 14.0f;     // p' <= 2^14 (fp16-safe)
constexpr int KROW_B = 80;                    // 16 data words + 4 pad
constexpr int KIMG_B = 2 * TK * KROW_B;       // 10240 (2 bf16 splits)
constexpr int VROW_B = 144;                   // 32 data words + 4 pad
constexpr int VIMG_B = CIN * VROW_B;          // 4608 (single fp16 image)
// smem layout (attn)
constexpr int SM_K  = 0;                      // 2 x 10240
constexpr int SM_V  = 2 * KIMG_B;             // 20480: 2 x 4608
constexpr int SM_W  = SM_V + 2 * VIMG_B;      // 29696: WovP 4096B
constexpr int SM_B2 = SM_W + 4096;            // 33792: 128B
constexpr int SM_OV = SM_B2 + 128;            // 33920: 128*33*4
constexpr int SM_TOTAL = SM_OV + 128 * 33 * 4; // 50816
}

// global scratch (allocation-free rule; zero-initialized at module load)
__device__ __align__(16) float g_WovP[CIN * CIN];  // [j][c] = (Wo Wv)[c][j]
__device__ __align__(16) float g_b2[CIN];          // Wo bv + bo
__device__ __align__(16) unsigned char g_Kimg[BATCH * NKT * KIMG_B]; // 5.24MB
__device__ __align__(16) unsigned char g_Vimg[BATCH * NKT * VIMG_B]; // 2.36MB
__device__ __align__(16) uint32_t g_Rw[2 * BATCH * NPIX * 16];       // 4MB
__device__ float    g_rn[BATCH * NPIX];            // ||r_n|| (log2e-scaled)
__device__ unsigned g_M2[BATCH];                   // bits of max ||x||^2
// (no reset needed: zero-init at load; atomicMax idempotent across replays)

// ---------------- helpers ----------------
__device__ __forceinline__ void mma_bf16(float* d, const uint32_t* a, const uint32_t* b) {
    asm("mma.sync.aligned.m16n8k16.row.col.f32.bf16.bf16.f32 "
        "{%0,%1,%2,%3}, {%4,%5,%6,%7}, {%8,%9}, {%0,%1,%2,%3};"
        : "+f"(d[0]), "+f"(d[1]), "+f"(d[2]), "+f"(d[3])
        : "r"(a[0]), "r"(a[1]), "r"(a[2]), "r"(a[3]), "r"(b[0]), "r"(b[1]));
}
__device__ __forceinline__ void mma_f16(float* d, const uint32_t* a, const uint32_t* b) {
    asm("mma.sync.aligned.m16n8k16.row.col.f32.f16.f16.f32 "
        "{%0,%1,%2,%3}, {%4,%5,%6,%7}, {%8,%9}, {%0,%1,%2,%3};"
        : "+f"(d[0]), "+f"(d[1]), "+f"(d[2]), "+f"(d[3])
        : "r"(a[0]), "r"(a[1]), "r"(a[2]), "r"(a[3]), "r"(b[0]), "r"(b[1]));
}
__device__ __forceinline__ void ldsm4(uint32_t* r, uint32_t addr) {
    asm volatile("ldmatrix.sync.aligned.m8n8.x4.shared.b16 {%0,%1,%2,%3}, [%4];"
        : "=r"(r[0]), "=r"(r[1]), "=r"(r[2]), "=r"(r[3]) : "r"(addr));
}
__device__ __forceinline__ uint32_t pk_bf(float lo, float hi) {   // {hi:lo}
    uint32_t r;
    asm("cvt.rn.satfinite.bf16x2.f32 %0, %1, %2;" : "=r"(r) : "f"(hi), "f"(lo));
    return r;
}
__device__ __forceinline__ uint32_t pk_f16(float lo, float hi) {  // {hi:lo}
    uint32_t r;
    asm("cvt.rn.f16x2.f32 %0, %1, %2;" : "=r"(r) : "f"(hi), "f"(lo));
    return r;
}
__device__ __forceinline__ float ex2f(float a) {
    float p; asm("ex2.approx.f32 %0, %1;" : "=f"(p) : "f"(a)); return p;
}
__device__ __forceinline__ uint32_t sm_u32(const void* p) {
    uint32_t a;
    asm("{ .reg .u64 t; cvta.to.shared.u64 t, %1; cvt.u32.u64 %0, t; }" : "=r"(a) : "l"(p));
    return a;
}
__device__ __forceinline__ void cp16(uint32_t s, const void* g) {
    asm volatile("cp.async.cg.shared.global [%0], [%1], 16;" :: "r"(s), "l"(g));
}
__device__ __forceinline__ void cp_commit() { asm volatile("cp.async.commit_group;"); }
template<int N> __device__ __forceinline__ void cp_wait() {
    asm volatile("cp.async.wait_group %0;" :: "n"(N));
}

// ---------------------------------------------------------------------------
// Precursor: At/cv in-block, then r-projection + images + norms.
// Block (0,0) additionally computes g_WovP / g_b2 (derive kernel folded here).
// (BYTE-IDENTICAL to R12's tq_kernel.)
// ---------------------------------------------------------------------------
__global__ void tq_kernel(const float* __restrict__ x, const float* __restrict__ wq,
                          const float* __restrict__ bq, const float* __restrict__ wk,
                          const float* __restrict__ wv, const float* __restrict__ wo,
                          const float* __restrict__ bv, const float* __restrict__ bo) {
    __shared__ float sA[CIN * CIN];
    __shared__ float scv[CIN];
    __shared__ float swk[2048], swq[2048];
    int tid = threadIdx.x;                         // 256
    int b = blockIdx.y;
    int n = blockIdx.x * 256 + tid;

    for (int i = tid; i < 2048; i += 256) { swk[i] = wk[i]; swq[i] = wq[i]; }
    __syncthreads();
#pragma unroll
    for (int e = 0; e < 4; ++e) {
        int idx = tid * 4 + e;
        int j = idx >> 5, i = idx & 31;
        float a = 0.f;
#pragma unroll 8
        for (int o = 0; o < COUT; ++o) a += swk[o * 32 + i] * swq[o * 32 + j];
        sA[j * 32 + i] = a * LOG2E;
    }
    if (tid < 32) {
        float c = 0.f;
        for (int o = 0; o < COUT; ++o) c += bq[o] * swk[o * 32 + tid];
        scv[tid] = c * LOG2E;
    }
    __syncthreads();

    // derive-fold: ONE block computes WovP/b2 (swk/swq free for reuse now)
    if (blockIdx.x == 0 && blockIdx.y == 0) {
        for (int i = tid; i < 2048; i += 256) { swk[i] = wv[i]; swq[i] = wo[i]; }
        __syncthreads();
#pragma unroll
        for (int e = 0; e < 4; ++e) {
            int idx = tid * 4 + e;
            int j = idx >> 5, i = idx & 31;
            float w = 0.f;
#pragma unroll 8
            for (int cc = 0; cc < COUT; ++cc) w += swq[j * 64 + cc] * swk[cc * 32 + i];
            g_WovP[i * CIN + j] = w;
        }
        if (tid < 32) {
            float bb = bo[tid];
#pragma unroll 8
            for (int cc = 0; cc < COUT; ++cc) bb += swq[tid * 64 + cc] * bv[cc];
            g_b2[tid] = bb;
        }
    }

    float xv[CIN];
#pragma unroll
    for (int c = 0; c < CIN; ++c) xv[c] = x[((size_t)b * CIN + c) * NPIX + n];
    float r[CIN];
#pragma unroll
    for (int i = 0; i < CIN; ++i) r[i] = scv[i];
#pragma unroll
    for (int j = 0; j < CIN; ++j) {
        float v = xv[j];
#pragma unroll
        for (int i = 0; i < CIN; ++i) r[i] += sA[j * CIN + i] * v;
    }

    // norms for the provable softmax shift
    float nx2 = 0.f, nr2 = 0.f;
#pragma unroll
    for (int c = 0; c < CIN; ++c) { nx2 += xv[c] * xv[c]; nr2 += r[c] * r[c]; }
    atomicMax(&g_M2[b], __float_as_uint(nx2));     // positive floats: uint order
    g_rn[(size_t)b * NPIX + n] = sqrtf(nr2);

    int kt = n >> 6, kl = n & 63;
    uint32_t* K0 = (uint32_t*)(g_Kimg + (size_t)(b * NKT + kt) * KIMG_B) + kl * 20;
    uint32_t* K1 = K0 + TK * 20;
    unsigned char* V0 = g_Vimg + (size_t)(b * NKT + kt) * VIMG_B;
    uint32_t* R0 = g_Rw + ((size_t)b * NPIX + n) * 16;
    uint32_t* R1 = R0 + (size_t)BATCH * NPIX * 16;

#pragma unroll
    for (int w = 0; w < 16; ++w) {
        float va = xv[2 * w], vb = xv[2 * w + 1];
        __nv_bfloat16 a1 = __float2bfloat16(va), b1 = __float2bfloat16(vb);
        float a1f = __bfloat162float(a1), b1f = __bfloat162float(b1);
        K0[w] = pk_bf(a1f, b1f);
        K1[w] = pk_bf(va - a1f, vb - b1f);
        float ra = r[2 * w], rb = r[2 * w + 1];
        __nv_bfloat16 c1 = __float2bfloat16(ra), d1 = __float2bfloat16(rb);
        float c1f = __bfloat162float(c1), d1f = __bfloat162float(d1);
        R0[w] = pk_bf(c1f, d1f);
        R1[w] = pk_bf(ra - c1f, rb - d1f);
    }
    K0[16] = K0[17] = K0[18] = K0[19] = 0u;
    K1[16] = K1[17] = K1[18] = K1[19] = 0u;
#pragma unroll
    for (int c = 0; c < CIN; ++c)
        *(__half*)(V0 + c * VROW_B + kl * 2) = __float2half(xv[c]);
}

// ---------------------------------------------------------------------------
// HMMA flash attention. 128 threads = 4 warps x 32 query rows (m=2, R9 shape).
// ONLY change vs R12: fragment loads via ldmatrix.x4 (same bytes/values).
// ---------------------------------------------------------------------------
__global__ __launch_bounds__(128, 2) void attn_kernel(const float* __restrict__ xin,
                                                      float* __restrict__ out) {
    extern __shared__ unsigned char sm[];
    const int tid  = threadIdx.x, wid = tid >> 5, lane = tid & 31;
    const int tg   = lane >> 2, la = lane & 3;
    const int b    = blockIdx.x >> 5, qt = blockIdx.x & 31;
    const uint32_t smb = sm_u32(sm);

    float* sW  = (float*)(sm + SM_W);
    float* sB2 = (float*)(sm + SM_B2);
    float* sOv = (float*)(sm + SM_OV);
    for (int i = tid; i < CIN * CIN; i += 128) sW[i] = g_WovP[i];
    if (tid < CIN) sB2[tid] = g_b2[tid];

    // per-row S init: OFF - ||r_row|| * max||x||  (provable fp16-safe shift)
    const float Mb = sqrtf(__uint_as_float(g_M2[b]));
    float sh[2][2];
#pragma unroll
    for (int m = 0; m < 2; ++m)
#pragma unroll
        for (int h = 0; h < 2; ++h) {
            int row = qt * MQ + 32 * wid + 16 * m + 8 * h + tg;
            sh[m][h] = OFF - g_rn[(size_t)b * NPIX + row] * Mb;
        }

    // R fragments (resident): Ra[split][m][kblk][4]
    uint32_t Ra[2][2][2][4];
#pragma unroll
    for (int s = 0; s < 2; ++s)
#pragma unroll
        for (int m = 0; m < 2; ++m) {
            int qr = qt * MQ + 32 * wid + 16 * m + tg;
            const uint32_t* p0 = g_Rw + (((size_t)s * BATCH + b) * NPIX + qr) * 16;
            const uint32_t* p8 = p0 + 8 * 16;
#pragma unroll
            for (int k = 0; k < 2; ++k) {
                Ra[s][m][k][0] = p0[8 * k + la];
                Ra[s][m][k][1] = p8[8 * k + la];
                Ra[s][m][k][2] = p0[8 * k + la + 4];
                Ra[s][m][k][3] = p8[8 * k + la + 4];
            }
        }

    float O[2][4][4];
#pragma unroll
    for (int m = 0; m < 2; ++m)
#pragma unroll
        for (int c = 0; c < 4; ++c)
#pragma unroll
            for (int e = 0; e < 4; ++e) O[m][c][e] = 0.f;
    float l4[4] = {0.f, 0.f, 0.f, 0.f};

    // ldmatrix per-thread address components (row = lane&7, tile = lane>>3)
    const uint32_t lmK = (uint32_t)((lane & 7) * KROW_B + (lane >> 3) * 16);
    const uint32_t lmV = (uint32_t)((lane & 7) * VROW_B + (lane >> 3) * 16);

    // stage tile 0
    {
        const uint4* Ks = (const uint4*)(g_Kimg + (size_t)(b * NKT + 0) * KIMG_B);
        const uint4* Vs = (const uint4*)(g_Vimg + (size_t)(b * NKT + 0) * VIMG_B);
        for (int i = tid; i < KIMG_B / 16; i += 128) cp16(smb + SM_K + i * 16, Ks + i);
        for (int i = tid; i < VIMG_B / 16; i += 128) cp16(smb + SM_V + i * 16, Vs + i);
        cp_commit();
    }

#pragma unroll 1
    for (int t = 0; t < NKT; ++t) {
        if (t + 1 < NKT) {
            int nb = (t + 1) & 1;
            const uint4* Ks = (const uint4*)(g_Kimg + (size_t)(b * NKT + t + 1) * KIMG_B);
            const uint4* Vs = (const uint4*)(g_Vimg + (size_t)(b * NKT + t + 1) * VIMG_B);
            for (int i = tid; i < KIMG_B / 16; i += 128)
                cp16(smb + SM_K + nb * KIMG_B + i * 16, Ks + i);
            for (int i = tid; i < VIMG_B / 16; i += 128)
                cp16(smb + SM_V + nb * VIMG_B + i * 16, Vs + i);
            cp_commit();
            cp_wait<1>();
        } else {
            cp_wait<0>();
        }
        __syncthreads();
        const uint32_t kbase = smb + SM_K + (uint32_t)((t & 1) * KIMG_B) + lmK;
        const uint32_t vbase = smb + SM_V + (uint32_t)((t & 1) * VIMG_B) + lmV;

        // ---- QK: S = R.K^T + (OFF - bound_row)  (3 bf16 split products) ----
        float S[2][8][4];
#pragma unroll
        for (int m = 0; m < 2; ++m)
#pragma unroll
            for (int j = 0; j < 8; ++j) {
                S[m][j][0] = sh[m][0]; S[m][j][1] = sh[m][0];
                S[m][j][2] = sh[m][1]; S[m][j][3] = sh[m][1];
            }

#pragma unroll
        for (int bs = 0; bs < 2; ++bs) {
            uint32_t Bf[8][2][2];
#pragma unroll
            for (int j = 0; j < 8; ++j) {
                uint32_t r[4];
                ldsm4(r, kbase + (uint32_t)(bs * (TK * KROW_B) + j * 8 * KROW_B));
                Bf[j][0][0] = r[0]; Bf[j][0][1] = r[1];
                Bf[j][1][0] = r[2]; Bf[j][1][1] = r[3];
            }
            const int nas = bs ? 1 : 2;   // (R1,K1),(R2,K1),(R1,K2)
            for (int as = 0; as < nas; ++as)
#pragma unroll
                for (int m = 0; m < 2; ++m)
#pragma unroll
                    for (int j = 0; j < 8; ++j)
#pragma unroll
                        for (int k = 0; k < 2; ++k)
                            mma_bf16(S[m][j], Ra[as][m][k], Bf[j][k]);
        }

        // ---- softmax -> P fp16 fragments (arg <= OFF, overflow-free) ----
        uint32_t P[2][4][4];
#pragma unroll
        for (int m = 0; m < 2; ++m)
#pragma unroll
            for (int j = 0; j < 8; ++j) {
                float p0 = ex2f(S[m][j][0]), p1 = ex2f(S[m][j][1]);
                float p2 = ex2f(S[m][j][2]), p3 = ex2f(S[m][j][3]);
                l4[2 * m]     += p0 + p1;
                l4[2 * m + 1] += p2 + p3;
                int kk = j >> 1, o = (j & 1) * 2;
                P[m][kk][o]     = pk_f16(p0, p1);
                P[m][kk][o + 1] = pk_f16(p2, p3);
            }

        // ---- PV: O += P.V (single fp16 product) ----
        {
            uint32_t Vf[4][4][2];
#pragma unroll
            for (int c = 0; c < 4; ++c) {
                uint32_t r0[4], r1[4];
                ldsm4(r0, vbase + (uint32_t)(c * 8 * VROW_B));
                ldsm4(r1, vbase + (uint32_t)(c * 8 * VROW_B + 64));
                Vf[c][0][0] = r0[0]; Vf[c][0][1] = r0[1];
                Vf[c][1][0] = r0[2]; Vf[c][1][1] = r0[3];
                Vf[c][2][0] = r1[0]; Vf[c][2][1] = r1[1];
                Vf[c][3][0] = r1[2]; Vf[c][3][1] = r1[3];
            }
#pragma unroll
            for (int m = 0; m < 2; ++m)
#pragma unroll
                for (int c = 0; c < 4; ++c)
#pragma unroll
                    for (int k = 0; k < 4; ++k)
                        mma_f16(O[m][c], P[m][k], Vf[c][k]);
        }
        __syncthreads();
    }

    // ---- epilogue: l reduce (across la), normalize, store ov to smem ----
#pragma unroll
    for (int i = 0; i < 4; ++i) {
        l4[i] += __shfl_xor_sync(0xFFFFFFFFu, l4[i], 1);
        l4[i] += __shfl_xor_sync(0xFFFFFFFFu, l4[i], 2);
        asm("rcp.approx.f32 %0, %1;" : "+f"(l4[i]) : "f"(l4[i]));
    }
#pragma unroll
    for (int m = 0; m < 2; ++m)
#pragma unroll
        for (int h = 0; h < 2; ++h) {
            int row = 32 * wid + 16 * m + 8 * h + tg;
            float inv = l4[2 * m + h];
#pragma unroll
            for (int c = 0; c < 4; ++c) {
                sOv[row * 33 + 8 * c + 2 * la]     = O[m][c][2 * h]     * inv;
                sOv[row * 33 + 8 * c + 2 * la + 1] = O[m][c][2 * h + 1] * inv;
            }
        }
    __syncthreads();

    // ---- fused projection + bias + residual (1 query/thread) ----
    float ov[CIN], y[CIN];
#pragma unroll
    for (int c = 0; c < CIN; ++c) ov[c] = sOv[tid * 33 + c];
#pragma unroll
    for (int c = 0; c < CIN; ++c) y[c] = sB2[c];
#pragma unroll 4
    for (int j = 0; j < CIN; ++j) {
        float pj = ov[j];
        const float* wp = sW + j * CIN;
#pragma unroll
        for (int c = 0; c < CIN; ++c) y[c] += pj * wp[c];
    }
    int n = qt * MQ + tid;
    const float* xp = xin + (size_t)b * CIN * NPIX + n;
    float*       op = out + (size_t)b * CIN * NPIX + n;
#pragma unroll
    for (int c = 0; c < CIN; ++c)
        op[(size_t)c * NPIX] = y[c] + xp[(size_t)c * NPIX];
}

// ---------------------------------------------------------------------------
extern "C" void kernel_launch(void* const* d_in, const int* in_sizes, int n_in,
                              void* d_out, int out_size) {
    (void)in_sizes; (void)n_in; (void)out_size;
    const float* x  = (const float*)d_in[0];
    const float* wq = (const float*)d_in[1];
    const float* bq = (const float*)d_in[2];
    const float* wk = (const float*)d_in[3];
    // d_in[4] = bk: cancels in softmax, unused
    const float* wv = (const float*)d_in[5];
    const float* bv = (const float*)d_in[6];
    const float* wo = (const float*)d_in[7];
    const float* bo = (const float*)d_in[8];
    float* out = (float*)d_out;

    cudaFuncSetAttribute(attn_kernel, cudaFuncAttributeMaxDynamicSharedMemorySize, SM_TOTAL);

    tq_kernel<<<dim3(NPIX / 256, BATCH), 256>>>(x, wq, bq, wk, wv, wo, bv, bo);
    attn_kernel<<<BATCH * (NPIX / MQ), 256 / 2, SM_TOTAL>>>(x, out);
}

// round 15
// speedup vs baseline: 1.1632x; 1.0402x over previous
#include <cuda_runtime.h>
#include <cuda_bf16.h>
#include <cuda_fp16.h>
#include <cstdint>

// ---------------------------------------------------------------------------
// SAM spatial self-attention, reduced algebra + HMMA (mma.sync) flash.
//   scores: s_nm = r_n . x_m,  r = log2e*((Wq^T Wk)^T x + Wk^T bq)
//   out:    y = (Wo Wv)(softmax(s) X) + (Wo bv + bo) + x
// QK: bf16 2-way splits, 3 of 4 cross products.
// PV: single fp16 product; fp16-safe via the provable per-query shift
//   s <= ||r_n|| * max_m ||x_m|| (Cauchy-Schwarz), p' = 2^(s-bound+14) <= 2^14.
// R15: attn byte-identical to R14 (ldmatrix fragment loads, measured 103.8us).
// ONE change: the WovP/b2 derive moves from a straggler on tq block (0,0) to
// a DEDICATED block (blockIdx.x==16) that runs in parallel with the 128 image
// blocks — R12..R14 carried a ~7us serial tail on the tq grid.
// ---------------------------------------------------------------------------

namespace {
constexpr int BATCH = 8, CIN = 32, COUT = 64, NPIX = 4096;
constexpr int MQ  = 128;           // queries per CTA
constexpr int TK  = 64;            // keys per tile
constexpr int NKT = NPIX / TK;     // 64
constexpr float LOG2E = 1.4426950408889634f;
constexpr float OFF   = 14.0f;     // p' <= 2^14 (fp16-safe)
constexpr int KROW_B = 80;                    // 16 data words + 4 pad
constexpr int KIMG_B = 2 * TK * KROW_B;       // 10240 (2 bf16 splits)
constexpr int VROW_B = 144;                   // 32 data words + 4 pad
constexpr int VIMG_B = CIN * VROW_B;          // 4608 (single fp16 image)
// smem layout (attn)
constexpr int SM_K  = 0;                      // 2 x 10240
constexpr int SM_V  = 2 * KIMG_B;             // 20480: 2 x 4608
constexpr int SM_W  = SM_V + 2 * VIMG_B;      // 29696: WovP 4096B
constexpr int SM_B2 = SM_W + 4096;            // 33792: 128B
constexpr int SM_OV = SM_B2 + 128;            // 33920: 128*33*4
constexpr int SM_TOTAL = SM_OV + 128 * 33 * 4; // 50816
}

// global scratch (allocation-free rule; zero-initialized at module load)
__device__ __align__(16) float g_WovP[CIN * CIN];  // [j][c] = (Wo Wv)[c][j]
__device__ __align__(16) float g_b2[CIN];          // Wo bv + bo
__device__ __align__(16) unsigned char g_Kimg[BATCH * NKT * KIMG_B]; // 5.24MB
__device__ __align__(16) unsigned char g_Vimg[BATCH * NKT * VIMG_B]; // 2.36MB
__device__ __align__(16) uint32_t g_Rw[2 * BATCH * NPIX * 16];       // 4MB
__device__ float    g_rn[BATCH * NPIX];            // ||r_n|| (log2e-scaled)
__device__ unsigned g_M2[BATCH];                   // bits of max ||x||^2
// (no reset needed: zero-init at load; atomicMax idempotent across replays)

// ---------------- helpers ----------------
__device__ __forceinline__ void mma_bf16(float* d, const uint32_t* a, const uint32_t* b) {
    asm("mma.sync.aligned.m16n8k16.row.col.f32.bf16.bf16.f32 "
        "{%0,%1,%2,%3}, {%4,%5,%6,%7}, {%8,%9}, {%0,%1,%2,%3};"
        : "+f"(d[0]), "+f"(d[1]), "+f"(d[2]), "+f"(d[3])
        : "r"(a[0]), "r"(a[1]), "r"(a[2]), "r"(a[3]), "r"(b[0]), "r"(b[1]));
}
__device__ __forceinline__ void mma_f16(float* d, const uint32_t* a, const uint32_t* b) {
    asm("mma.sync.aligned.m16n8k16.row.col.f32.f16.f16.f32 "
        "{%0,%1,%2,%3}, {%4,%5,%6,%7}, {%8,%9}, {%0,%1,%2,%3};"
        : "+f"(d[0]), "+f"(d[1]), "+f"(d[2]), "+f"(d[3])
        : "r"(a[0]), "r"(a[1]), "r"(a[2]), "r"(a[3]), "r"(b[0]), "r"(b[1]));
}
__device__ __forceinline__ void ldsm4(uint32_t* r, uint32_t addr) {
    asm volatile("ldmatrix.sync.aligned.m8n8.x4.shared.b16 {%0,%1,%2,%3}, [%4];"
        : "=r"(r[0]), "=r"(r[1]), "=r"(r[2]), "=r"(r[3]) : "r"(addr));
}
__device__ __forceinline__ uint32_t pk_bf(float lo, float hi) {   // {hi:lo}
    uint32_t r;
    asm("cvt.rn.satfinite.bf16x2.f32 %0, %1, %2;" : "=r"(r) : "f"(hi), "f"(lo));
    return r;
}
__device__ __forceinline__ uint32_t pk_f16(float lo, float hi) {  // {hi:lo}
    uint32_t r;
    asm("cvt.rn.f16x2.f32 %0, %1, %2;" : "=r"(r) : "f"(hi), "f"(lo));
    return r;
}
__device__ __forceinline__ float ex2f(float a) {
    float p; asm("ex2.approx.f32 %0, %1;" : "=f"(p) : "f"(a)); return p;
}
__device__ __forceinline__ uint32_t sm_u32(const void* p) {
    uint32_t a;
    asm("{ .reg .u64 t; cvta.to.shared.u64 t, %1; cvt.u32.u64 %0, t; }" : "=r"(a) : "l"(p));
    return a;
}
__device__ __forceinline__ void cp16(uint32_t s, const void* g) {
    asm volatile("cp.async.cg.shared.global [%0], [%1], 16;" :: "r"(s), "l"(g));
}
__device__ __forceinline__ void cp_commit() { asm volatile("cp.async.commit_group;"); }
template<int N> __device__ __forceinline__ void cp_wait() {
    asm volatile("cp.async.wait_group %0;" :: "n"(N));
}

// ---------------------------------------------------------------------------
// Precursor: At/cv in-block, then r-projection + images + norms.
// blockIdx.x == 16: DEDICATED derive block — computes g_WovP / g_b2 in
// parallel with the image blocks (no straggler on the image path).
// ---------------------------------------------------------------------------
__global__ void tq_kernel(const float* __restrict__ x, const float* __restrict__ wq,
                          const float* __restrict__ bq, const float* __restrict__ wk,
                          const float* __restrict__ wv, const float* __restrict__ wo,
                          const float* __restrict__ bv, const float* __restrict__ bo) {
    __shared__ float sA[CIN * CIN];
    __shared__ float scv[CIN];
    __shared__ float swk[2048], swq[2048];
    int tid = threadIdx.x;                         // 256
    int b = blockIdx.y;

    if (blockIdx.x == 16) {                        // dedicated derive block
        if (b != 0) return;
        for (int i = tid; i < 2048; i += 256) { swk[i] = wv[i]; swq[i] = wo[i]; }
        __syncthreads();
#pragma unroll
        for (int e = 0; e < 4; ++e) {
            int idx = tid * 4 + e;
            int j = idx >> 5, i = idx & 31;
            float w = 0.f;
#pragma unroll 8
            for (int cc = 0; cc < COUT; ++cc) w += swq[j * 64 + cc] * swk[cc * 32 + i];
            g_WovP[i * CIN + j] = w;
        }
        if (tid < 32) {
            float bb = bo[tid];
#pragma unroll 8
            for (int cc = 0; cc < COUT; ++cc) bb += swq[tid * 64 + cc] * bv[cc];
            g_b2[tid] = bb;
        }
        return;
    }

    int n = blockIdx.x * 256 + tid;

    for (int i = tid; i < 2048; i += 256) { swk[i] = wk[i]; swq[i] = wq[i]; }
    __syncthreads();
#pragma unroll
    for (int e = 0; e < 4; ++e) {
        int idx = tid * 4 + e;
        int j = idx >> 5, i = idx & 31;
        float a = 0.f;
#pragma unroll 8
        for (int o = 0; o < COUT; ++o) a += swk[o * 32 + i] * swq[o * 32 + j];
        sA[j * 32 + i] = a * LOG2E;
    }
    if (tid < 32) {
        float c = 0.f;
        for (int o = 0; o < COUT; ++o) c += bq[o] * swk[o * 32 + tid];
        scv[tid] = c * LOG2E;
    }
    __syncthreads();

    float xv[CIN];
#pragma unroll
    for (int c = 0; c < CIN; ++c) xv[c] = x[((size_t)b * CIN + c) * NPIX + n];
    float r[CIN];
#pragma unroll
    for (int i = 0; i < CIN; ++i) r[i] = scv[i];
#pragma unroll
    for (int j = 0; j < CIN; ++j) {
        float v = xv[j];
#pragma unroll
        for (int i = 0; i < CIN; ++i) r[i] += sA[j * CIN + i] * v;
    }

    // norms for the provable softmax shift
    float nx2 = 0.f, nr2 = 0.f;
#pragma unroll
    for (int c = 0; c < CIN; ++c) { nx2 += xv[c] * xv[c]; nr2 += r[c] * r[c]; }
    atomicMax(&g_M2[b], __float_as_uint(nx2));     // positive floats: uint order
    g_rn[(size_t)b * NPIX + n] = sqrtf(nr2);

    int kt = n >> 6, kl = n & 63;
    uint32_t* K0 = (uint32_t*)(g_Kimg + (size_t)(b * NKT + kt) * KIMG_B) + kl * 20;
    uint32_t* K1 = K0 + TK * 20;
    unsigned char* V0 = g_Vimg + (size_t)(b * NKT + kt) * VIMG_B;
    uint32_t* R0 = g_Rw + ((size_t)b * NPIX + n) * 16;
    uint32_t* R1 = R0 + (size_t)BATCH * NPIX * 16;

#pragma unroll
    for (int w = 0; w < 16; ++w) {
        float va = xv[2 * w], vb = xv[2 * w + 1];
        __nv_bfloat16 a1 = __float2bfloat16(va), b1 = __float2bfloat16(vb);
        float a1f = __bfloat162float(a1), b1f = __bfloat162float(b1);
        K0[w] = pk_bf(a1f, b1f);
        K1[w] = pk_bf(va - a1f, vb - b1f);
        float ra = r[2 * w], rb = r[2 * w + 1];
        __nv_bfloat16 c1 = __float2bfloat16(ra), d1 = __float2bfloat16(rb);
        float c1f = __bfloat162float(c1), d1f = __bfloat162float(d1);
        R0[w] = pk_bf(c1f, d1f);
        R1[w] = pk_bf(ra - c1f, rb - d1f);
    }
    K0[16] = K0[17] = K0[18] = K0[19] = 0u;
    K1[16] = K1[17] = K1[18] = K1[19] = 0u;
#pragma unroll
    for (int c = 0; c < CIN; ++c)
        *(__half*)(V0 + c * VROW_B + kl * 2) = __float2half(xv[c]);
}

// ---------------------------------------------------------------------------
// HMMA flash attention. 128 threads = 4 warps x 32 query rows (m=2, R9 shape).
// BYTE-IDENTICAL to R14's attn (ldmatrix fragment loads): do not touch.
// ---------------------------------------------------------------------------
__global__ __launch_bounds__(128, 2) void attn_kernel(const float* __restrict__ xin,
                                                      float* __restrict__ out) {
    extern __shared__ unsigned char sm[];
    const int tid  = threadIdx.x, wid = tid >> 5, lane = tid & 31;
    const int tg   = lane >> 2, la = lane & 3;
    const int b    = blockIdx.x >> 5, qt = blockIdx.x & 31;
    const uint32_t smb = sm_u32(sm);

    float* sW  = (float*)(sm + SM_W);
    float* sB2 = (float*)(sm + SM_B2);
    float* sOv = (float*)(sm + SM_OV);
    for (int i = tid; i < CIN * CIN; i += 128) sW[i] = g_WovP[i];
    if (tid < CIN) sB2[tid] = g_b2[tid];

    // per-row S init: OFF - ||r_row|| * max||x||  (provable fp16-safe shift)
    const float Mb = sqrtf(__uint_as_float(g_M2[b]));
    float sh[2][2];
#pragma unroll
    for (int m = 0; m < 2; ++m)
#pragma unroll
        for (int h = 0; h < 2; ++h) {
            int row = qt * MQ + 32 * wid + 16 * m + 8 * h + tg;
            sh[m][h] = OFF - g_rn[(size_t)b * NPIX + row] * Mb;
        }

    // R fragments (resident): Ra[split][m][kblk][4]
    uint32_t Ra[2][2][2][4];
#pragma unroll
    for (int s = 0; s < 2; ++s)
#pragma unroll
        for (int m = 0; m < 2; ++m) {
            int qr = qt * MQ + 32 * wid + 16 * m + tg;
            const uint32_t* p0 = g_Rw + (((size_t)s * BATCH + b) * NPIX + qr) * 16;
            const uint32_t* p8 = p0 + 8 * 16;
#pragma unroll
            for (int k = 0; k < 2; ++k) {
                Ra[s][m][k][0] = p0[8 * k + la];
                Ra[s][m][k][1] = p8[8 * k + la];
                Ra[s][m][k][2] = p0[8 * k + la + 4];
                Ra[s][m][k][3] = p8[8 * k + la + 4];
            }
        }

    float O[2][4][4];
#pragma unroll
    for (int m = 0; m < 2; ++m)
#pragma unroll
        for (int c = 0; c < 4; ++c)
#pragma unroll
            for (int e = 0; e < 4; ++e) O[m][c][e] = 0.f;
    float l4[4] = {0.f, 0.f, 0.f, 0.f};

    // ldmatrix per-thread address components (row = lane&7, tile = lane>>3)
    const uint32_t lmK = (uint32_t)((lane & 7) * KROW_B + (lane >> 3) * 16);
    const uint32_t lmV = (uint32_t)((lane & 7) * VROW_B + (lane >> 3) * 16);

    // stage tile 0
    {
        const uint4* Ks = (const uint4*)(g_Kimg + (size_t)(b * NKT + 0) * KIMG_B);
        const uint4* Vs = (const uint4*)(g_Vimg + (size_t)(b * NKT + 0) * VIMG_B);
        for (int i = tid; i < KIMG_B / 16; i += 128) cp16(smb + SM_K + i * 16, Ks + i);
        for (int i = tid; i < VIMG_B / 16; i += 128) cp16(smb + SM_V + i * 16, Vs + i);
        cp_commit();
    }

#pragma unroll 1
    for (int t = 0; t < NKT; ++t) {
        if (t + 1 < NKT) {
            int nb = (t + 1) & 1;
            const uint4* Ks = (const uint4*)(g_Kimg + (size_t)(b * NKT + t + 1) * KIMG_B);
            const uint4* Vs = (const uint4*)(g_Vimg + (size_t)(b * NKT + t + 1) * VIMG_B);
            for (int i = tid; i < KIMG_B / 16; i += 128)
                cp16(smb + SM_K + nb * KIMG_B + i * 16, Ks + i);
            for (int i = tid; i < VIMG_B / 16; i += 128)
                cp16(smb + SM_V + nb * VIMG_B + i * 16, Vs + i);
            cp_commit();
            cp_wait<1>();
        } else {
            cp_wait<0>();
        }
        __syncthreads();
        const uint32_t kbase = smb + SM_K + (uint32_t)((t & 1) * KIMG_B) + lmK;
        const uint32_t vbase = smb + SM_V + (uint32_t)((t & 1) * VIMG_B) + lmV;

        // ---- QK: S = R.K^T + (OFF - bound_row)  (3 bf16 split products) ----
        float S[2][8][4];
#pragma unroll
        for (int m = 0; m < 2; ++m)
#pragma unroll
            for (int j = 0; j < 8; ++j) {
                S[m][j][0] = sh[m][0]; S[m][j][1] = sh[m][0];
                S[m][j][2] = sh[m][1]; S[m][j][3] = sh[m][1];
            }

#pragma unroll
        for (int bs = 0; bs < 2; ++bs) {
            uint32_t Bf[8][2][2];
#pragma unroll
            for (int j = 0; j < 8; ++j) {
                uint32_t r[4];
                ldsm4(r, kbase + (uint32_t)(bs * (TK * KROW_B) + j * 8 * KROW_B));
                Bf[j][0][0] = r[0]; Bf[j][0][1] = r[1];
                Bf[j][1][0] = r[2]; Bf[j][1][1] = r[3];
            }
            const int nas = bs ? 1 : 2;   // (R1,K1),(R2,K1),(R1,K2)
            for (int as = 0; as < nas; ++as)
#pragma unroll
                for (int m = 0; m < 2; ++m)
#pragma unroll
                    for (int j = 0; j < 8; ++j)
#pragma unroll
                        for (int k = 0; k < 2; ++k)
                            mma_bf16(S[m][j], Ra[as][m][k], Bf[j][k]);
        }

        // ---- softmax -> P fp16 fragments (arg <= OFF, overflow-free) ----
        uint32_t P[2][4][4];
#pragma unroll
        for (int m = 0; m < 2; ++m)
#pragma unroll
            for (int j = 0; j < 8; ++j) {
                float p0 = ex2f(S[m][j][0]), p1 = ex2f(S[m][j][1]);
                float p2 = ex2f(S[m][j][2]), p3 = ex2f(S[m][j][3]);
                l4[2 * m]     += p0 + p1;
                l4[2 * m + 1] += p2 + p3;
                int kk = j >> 1, o = (j & 1) * 2;
                P[m][kk][o]     = pk_f16(p0, p1);
                P[m][kk][o + 1] = pk_f16(p2, p3);
            }

        // ---- PV: O += P.V (single fp16 product) ----
        {
            uint32_t Vf[4][4][2];
#pragma unroll
            for (int c = 0; c < 4; ++c) {
                uint32_t r0[4], r1[4];
                ldsm4(r0, vbase + (uint32_t)(c * 8 * VROW_B));
                ldsm4(r1, vbase + (uint32_t)(c * 8 * VROW_B + 64));
                Vf[c][0][0] = r0[0]; Vf[c][0][1] = r0[1];
                Vf[c][1][0] = r0[2]; Vf[c][1][1] = r0[3];
                Vf[c][2][0] = r1[0]; Vf[c][2][1] = r1[1];
                Vf[c][3][0] = r1[2]; Vf[c][3][1] = r1[3];
            }
#pragma unroll
            for (int m = 0; m < 2; ++m)
#pragma unroll
                for (int c = 0; c < 4; ++c)
#pragma unroll
                    for (int k = 0; k < 4; ++k)
                        mma_f16(O[m][c], P[m][k], Vf[c][k]);
        }
        __syncthreads();
    }

    // ---- epilogue: l reduce (across la), normalize, store ov to smem ----
#pragma unroll
    for (int i = 0; i < 4; ++i) {
        l4[i] += __shfl_xor_sync(0xFFFFFFFFu, l4[i], 1);
        l4[i] += __shfl_xor_sync(0xFFFFFFFFu, l4[i], 2);
        asm("rcp.approx.f32 %0, %1;" : "+f"(l4[i]) : "f"(l4[i]));
    }
#pragma unroll
    for (int m = 0; m < 2; ++m)
#pragma unroll
        for (int h = 0; h < 2; ++h) {
            int row = 32 * wid + 16 * m + 8 * h + tg;
            float inv = l4[2 * m + h];
#pragma unroll
            for (int c = 0; c < 4; ++c) {
                sOv[row * 33 + 8 * c + 2 * la]     = O[m][c][2 * h]     * inv;
                sOv[row * 33 + 8 * c + 2 * la + 1] = O[m][c][2 * h + 1] * inv;
            }
        }
    __syncthreads();

    // ---- fused projection + bias + residual (1 query/thread) ----
    float ov[CIN], y[CIN];
#pragma unroll
    for (int c = 0; c < CIN; ++c) ov[c] = sOv[tid * 33 + c];
#pragma unroll
    for (int c = 0; c < CIN; ++c) y[c] = sB2[c];
#pragma unroll 4
    for (int j = 0; j < CIN; ++j) {
        float pj = ov[j];
        const float* wp = sW + j * CIN;
#pragma unroll
        for (int c = 0; c < CIN; ++c) y[c] += pj * wp[c];
    }
    int n = qt * MQ + tid;
    const float* xp = xin + (size_t)b * CIN * NPIX + n;
    float*       op = out + (size_t)b * CIN * NPIX + n;
#pragma unroll
    for (int c = 0; c < CIN; ++c)
        op[(size_t)c * NPIX] = y[c] + xp[(size_t)c * NPIX];
}

// ---------------------------------------------------------------------------
extern "C" void kernel_launch(void* const* d_in, const int* in_sizes, int n_in,
                              void* d_out, int out_size) {
    (void)in_sizes; (void)n_in; (void)out_size;
    const float* x  = (const float*)d_in[0];
    const float* wq = (const float*)d_in[1];
    const float* bq = (const float*)d_in[2];
    const float* wk = (const float*)d_in[3];
    // d_in[4] = bk: cancels in softmax, unused
    const float* wv = (const float*)d_in[5];
    const float* bv = (const float*)d_in[6];
    const float* wo = (const float*)d_in[7];
    const float* bo = (const float*)d_in[8];
    float* out = (float*)d_out;

    cudaFuncSetAttribute(attn_kernel, cudaFuncAttributeMaxDynamicSharedMemorySize, SM_TOTAL);

    tq_kernel<<<dim3(NPIX / 256 + 1, BATCH), 256>>>(x, wq, bq, wk, wv, wo, bv, bo);
    attn_kernel<<<BATCH * (NPIX / MQ), 128, SM_TOTAL>>>(x, out);
}